// round 2
// baseline (speedup 1.0000x reference)
#include <cuda_runtime.h>
#include <cuda_bf16.h>
#include <math.h>

#define NN 50000
#define NE 800000
#define DD 128
#define NG 3
#define NTILES ((NN + 63) / 64)   // 782
#define NSCAN 13                  // ceil(50000/4096)

typedef unsigned long long ull;

// ---------------- scratch ----------------------------------------------------
__device__ int   d_deg[NG][NN];
__device__ int   d_start[NG][NN + 1];
__device__ int   d_cursor[NG][NN];
__device__ int   d_srcs[NG][NE];
__device__ float d_dinv[NG][NN];
__device__ float d_gsum[NG][DD];
__device__ int   d_bsum[NG][16];

// ---------------- helpers ----------------------------------------------------
__device__ __forceinline__ ull ffma2(ull a, ull b, ull c) {
    ull d;
    asm("fma.rn.f32x2 %0, %1, %2, %3;" : "=l"(d) : "l"(a), "l"(b), "l"(c));
    return d;
}
__device__ __forceinline__ ull lo64(float4 v) {
    ull r; asm("mov.b64 %0, {%1, %2};" : "=l"(r) : "f"(v.x), "f"(v.y)); return r;
}
__device__ __forceinline__ ull hi64(float4 v) {
    ull r; asm("mov.b64 %0, {%1, %2};" : "=l"(r) : "f"(v.z), "f"(v.w)); return r;
}
__device__ __forceinline__ void unpack64(ull p, float& lo, float& hi) {
    asm("mov.b64 {%0, %1}, %2;" : "=f"(lo), "=f"(hi) : "l"(p));
}

// ---------------- prep kernels -----------------------------------------------
__global__ void zero_kernel() {
    int i = blockIdx.x * blockDim.x + threadIdx.x;
    int stride = gridDim.x * blockDim.x;
    for (int j = i; j < NG * NN; j += stride) ((int*)d_deg)[j] = 0;
    for (int j = i; j < NG * DD; j += stride) ((float*)d_gsum)[j] = 0.0f;
}

__global__ void hist_kernel(const int* __restrict__ e1,
                            const int* __restrict__ e2,
                            const int* __restrict__ e3) {
    int g = blockIdx.y;
    const int* ei = (g == 0) ? e1 : ((g == 1) ? e2 : e3);
    const int4* dst4 = (const int4*)(ei + NE);
    int stride = gridDim.x * blockDim.x;
    for (int i = blockIdx.x * blockDim.x + threadIdx.x; i < NE / 4; i += stride) {
        int4 d = dst4[i];
        atomicAdd(&d_deg[g][d.x], 1);
        atomicAdd(&d_deg[g][d.y], 1);
        atomicAdd(&d_deg[g][d.z], 1);
        atomicAdd(&d_deg[g][d.w], 1);
    }
}

__global__ void scan_pass1() {   // grid (NSCAN, NG) x 256
    int g = blockIdx.y;
    int t = threadIdx.x;
    int base = blockIdx.x * 4096 + t * 16;
    int s = 0;
    #pragma unroll
    for (int i = 0; i < 16; i++) {
        int idx = base + i;
        if (idx < NN) s += d_deg[g][idx];
    }
    #pragma unroll
    for (int o = 16; o; o >>= 1) s += __shfl_down_sync(0xffffffffu, s, o);
    __shared__ int ws[8];
    if ((t & 31) == 0) ws[t >> 5] = s;
    __syncthreads();
    if (t == 0) {
        int v = 0;
        #pragma unroll
        for (int w = 0; w < 8; w++) v += ws[w];
        d_bsum[g][blockIdx.x] = v;
    }
}

__global__ void scan_pass2() {   // 1 block x 96
    int t = threadIdx.x;
    int g = t >> 5, l = t & 31;
    int v = (l < NSCAN) ? d_bsum[g][l] : 0;
    int incl = v;
    #pragma unroll
    for (int o = 1; o < 32; o <<= 1) {
        int y = __shfl_up_sync(0xffffffffu, incl, o);
        if (l >= o) incl += y;
    }
    if (l < NSCAN) d_bsum[g][l] = incl - v;
    if (l == 0) d_start[g][NN] = NE;
}

__global__ void scan_pass3() {   // grid (NSCAN, NG) x 256
    int g = blockIdx.y;
    int t = threadIdx.x;
    int base = blockIdx.x * 4096 + t * 16;
    int v[16];
    int s = 0;
    #pragma unroll
    for (int i = 0; i < 16; i++) {
        int idx = base + i;
        v[i] = (idx < NN) ? d_deg[g][idx] : 0;
        s += v[i];
    }
    int incl = s;
    #pragma unroll
    for (int o = 1; o < 32; o <<= 1) {
        int y = __shfl_up_sync(0xffffffffu, incl, o);
        if ((t & 31) >= o) incl += y;
    }
    __shared__ int ws[8];
    if ((t & 31) == 31) ws[t >> 5] = incl;
    __syncthreads();
    if (t == 0) {
        int run = 0;
        #pragma unroll
        for (int w = 0; w < 8; w++) { int tmp = ws[w]; ws[w] = run; run += tmp; }
    }
    __syncthreads();
    int run = d_bsum[g][blockIdx.x] + ws[t >> 5] + (incl - s);
    #pragma unroll
    for (int i = 0; i < 16; i++) {
        int idx = base + i;
        if (idx < NN) {
            d_start[g][idx]  = run;
            d_cursor[g][idx] = run;
            d_dinv[g][idx]   = rsqrtf((float)(v[i] + 1));
            run += v[i];
        }
    }
}

__global__ void fill_kernel(const int* __restrict__ e1,
                            const int* __restrict__ e2,
                            const int* __restrict__ e3) {
    int g = blockIdx.y;
    const int* ei = (g == 0) ? e1 : ((g == 1) ? e2 : e3);
    const int4* src4 = (const int4*)ei;
    const int4* dst4 = (const int4*)(ei + NE);
    int stride = gridDim.x * blockDim.x;
    int* srcs = d_srcs[g];
    int* cur  = d_cursor[g];
    for (int i = blockIdx.x * blockDim.x + threadIdx.x; i < NE / 4; i += stride) {
        int4 sv = src4[i];
        int4 dv = dst4[i];
        srcs[atomicAdd(&cur[dv.x], 1)] = sv.x;
        srcs[atomicAdd(&cur[dv.y], 1)] = sv.y;
        srcs[atomicAdd(&cur[dv.z], 1)] = sv.z;
        srcs[atomicAdd(&cur[dv.w], 1)] = sv.w;
    }
}

// ---------------- fused gather + GEMM + pooled sum -----------------------------
// smem: Wt[128][132] transposed W (67584 f), zs[64][128] (8192 f), bs[128]
#define WT_PITCH 132
#define SM_WT 0
#define SM_ZS (128 * WT_PITCH)
#define SM_BS (SM_ZS + 64 * 128)
#define SM_TOTAL_F (SM_BS + 128)

__global__ void __launch_bounds__(256, 2)
fused_kernel(const float* __restrict__ x1, const float* __restrict__ x2,
             const float* __restrict__ x3,
             const float* __restrict__ W1, const float* __restrict__ b1,
             const float* __restrict__ W2, const float* __restrict__ b2,
             const float* __restrict__ W3, const float* __restrict__ b3) {
    extern __shared__ float sm[];
    float* Ws = sm + SM_WT;
    float* zs = sm + SM_ZS;
    float* bs = sm + SM_BS;

    int g = blockIdx.y;
    const float4* x4 = (const float4*)((g == 0) ? x1 : ((g == 1) ? x2 : x3));
    const float* W = (g == 0) ? W1 : ((g == 1) ? W2 : W3);
    const float* b = (g == 0) ? b1 : ((g == 1) ? b2 : b3);

    int t = threadIdx.x;          // 256
    int tx = t & 31;
    int ty = t >> 5;

    // load transposed W: Ws[j*132 + k] = W[k*128 + j]
    for (int idx = t; idx < DD * DD; idx += 256) {
        int j = idx & 127, k = idx >> 7;
        Ws[j * WT_PITCH + k] = W[idx];
    }
    if (t < DD) bs[t] = b[t];

    const int*   srcs  = d_srcs[g];
    const float* dinv  = d_dinv[g];
    const int*   start = d_start[g];

    float colsum[4] = {0.f, 0.f, 0.f, 0.f};

    for (int tile = blockIdx.x; tile < NTILES; tile += gridDim.x) {
        int row0 = tile * 64;

        // ---- gather: warp ty handles rows ty*8 .. ty*8+7 ----
        #pragma unroll 1
        for (int rr = 0; rr < 8; rr++) {
            int r = ty * 8 + rr;
            int n = row0 + r;
            float4 res = make_float4(0.f, 0.f, 0.f, 0.f);
            if (n < NN) {
                int s = start[n];
                int e = start[n + 1];
                float4 acc = make_float4(0.f, 0.f, 0.f, 0.f);
                int i = s;
                for (; i + 4 <= e; i += 4) {
                    int s0 = srcs[i], s1 = srcs[i + 1], s2 = srcs[i + 2], s3 = srcs[i + 3];
                    float w0 = dinv[s0], w1 = dinv[s1], w2 = dinv[s2], w3 = dinv[s3];
                    float4 a0 = x4[s0 * 32 + tx];
                    float4 a1 = x4[s1 * 32 + tx];
                    float4 a2 = x4[s2 * 32 + tx];
                    float4 a3 = x4[s3 * 32 + tx];
                    acc.x += w0 * a0.x + w1 * a1.x + w2 * a2.x + w3 * a3.x;
                    acc.y += w0 * a0.y + w1 * a1.y + w2 * a2.y + w3 * a3.y;
                    acc.z += w0 * a0.z + w1 * a1.z + w2 * a2.z + w3 * a3.z;
                    acc.w += w0 * a0.w + w1 * a1.w + w2 * a2.w + w3 * a3.w;
                }
                for (; i < e; i++) {
                    int s0 = srcs[i];
                    float w0 = dinv[s0];
                    float4 a0 = x4[s0 * 32 + tx];
                    acc.x += w0 * a0.x; acc.y += w0 * a0.y;
                    acc.z += w0 * a0.z; acc.w += w0 * a0.w;
                }
                float di = dinv[n];
                float c2 = di * di;
                float4 self = x4[n * 32 + tx];
                res.x = di * acc.x + c2 * self.x;
                res.y = di * acc.y + c2 * self.y;
                res.z = di * acc.z + c2 * self.z;
                res.w = di * acc.w + c2 * self.w;
            }
            *(float4*)(zs + r * 128 + tx * 4) = res;
        }
        __syncthreads();

        // ---- GEMM: thread -> rows ty*8..+7, cols {tx, tx+32, tx+64, tx+96} ----
        // split-k parity in f32x2: .lo = even-k partial, .hi = odd-k partial
        ull acc[8][4];
        #pragma unroll
        for (int r = 0; r < 8; r++)
            #pragma unroll
            for (int c = 0; c < 4; c++) acc[r][c] = 0ull;

        #pragma unroll 4
        for (int k = 0; k < 128; k += 4) {
            float4 wq0 = *(const float4*)(Ws + (tx      ) * WT_PITCH + k);
            float4 wq1 = *(const float4*)(Ws + (tx + 32 ) * WT_PITCH + k);
            float4 wq2 = *(const float4*)(Ws + (tx + 64 ) * WT_PITCH + k);
            float4 wq3 = *(const float4*)(Ws + (tx + 96 ) * WT_PITCH + k);
            ull wl[4] = {lo64(wq0), lo64(wq1), lo64(wq2), lo64(wq3)};
            ull wh[4] = {hi64(wq0), hi64(wq1), hi64(wq2), hi64(wq3)};
            #pragma unroll
            for (int r = 0; r < 8; r++) {
                float4 zq = *(const float4*)(zs + (ty * 8 + r) * 128 + k);
                ull zl = lo64(zq);
                ull zh = hi64(zq);
                #pragma unroll
                for (int c = 0; c < 4; c++) {
                    acc[r][c] = ffma2(zl, wl[c], acc[r][c]);
                    acc[r][c] = ffma2(zh, wh[c], acc[r][c]);
                }
            }
        }

        // epilogue: +b, relu, accumulate column sums (guard valid rows)
        #pragma unroll
        for (int c = 0; c < 4; c++) {
            float bb = bs[tx + 32 * c];
            #pragma unroll
            for (int r = 0; r < 8; r++) {
                if (row0 + ty * 8 + r < NN) {
                    float lo, hi;
                    unpack64(acc[r][c], lo, hi);
                    colsum[c] += fmaxf(lo + hi + bb, 0.f);
                }
            }
        }
        __syncthreads();   // before next tile overwrites zs
    }

    // block reduction of colsum (reuse zs)
    float* red = zs;
    #pragma unroll
    for (int c = 0; c < 4; c++) red[ty * 128 + tx + 32 * c] = colsum[c];
    __syncthreads();
    if (ty == 0) {
        #pragma unroll
        for (int c = 0; c < 4; c++) {
            int col = tx + 32 * c;
            float s = 0.f;
            #pragma unroll
            for (int yy = 0; yy < 8; yy++) s += red[yy * 128 + col];
            atomicAdd(&d_gsum[g][col], s);
        }
    }
}

// ---------------- head --------------------------------------------------------
__global__ void finalize_kernel(const float* __restrict__ a1w, const float* __restrict__ a1b,
                                const float* __restrict__ a2w, const float* __restrict__ a2b,
                                const float* __restrict__ a3w, const float* __restrict__ a3b,
                                const float* __restrict__ f1w, const float* __restrict__ f1b,
                                const float* __restrict__ f2w, const float* __restrict__ f2b,
                                float* __restrict__ out) {
    __shared__ float xin[3 * DD];
    __shared__ float h1[DD];
    __shared__ float h2[DD];
    __shared__ float aw[4];
    __shared__ float xa[DD];
    int t = threadIdx.x;
    xin[t]          = d_gsum[0][t];
    xin[DD + t]     = d_gsum[1][t];
    xin[2 * DD + t] = d_gsum[2][t];
    __syncthreads();
    {
        float s = a1b[t];
        for (int j = 0; j < 3 * DD; j++) s += xin[j] * a1w[t * (3 * DD) + j];
        h1[t] = fmaxf(s, 0.f);
    }
    __syncthreads();
    {
        float s = a2b[t];
        for (int j = 0; j < DD; j++) s += h1[j] * a2w[t * DD + j];
        h2[t] = s;
    }
    __syncthreads();
    if (t < 3) {
        float s = a3b[t];
        for (int j = 0; j < DD; j++) s += fmaxf(h2[j], 0.f) * a3w[t * DD + j];
        aw[t] = s;
    }
    __syncthreads();
    if (t == 0) {
        float m = fmaxf(aw[0], fmaxf(aw[1], aw[2]));
        float e0 = expf(aw[0] - m), e1 = expf(aw[1] - m), e2 = expf(aw[2] - m);
        float S = e0 + e1 + e2;
        aw[0] = e0 / S; aw[1] = e1 / S; aw[2] = e2 / S;
    }
    __syncthreads();
    xa[t] = aw[0] * xin[t] + aw[1] * xin[DD + t] + aw[2] * xin[2 * DD + t];
    __syncthreads();
    float sg = f1b[t], sb = f2b[t];
    for (int j = 0; j < DD; j++) {
        float v = xa[j];
        sg += v * f1w[t * DD + j];
        sb += v * f2w[t * DD + j];
    }
    out[t]      = tanhf(sg);
    out[DD + t] = tanhf(sb);
}

// ---------------- launch ------------------------------------------------------
extern "C" void kernel_launch(void* const* d_in, const int* in_sizes, int n_in,
                              void* d_out, int out_size) {
    const float* x1 = (const float*)d_in[0];
    const float* x2 = (const float*)d_in[1];
    const float* x3 = (const float*)d_in[2];
    const int* e1 = (const int*)d_in[3];
    const int* e2 = (const int*)d_in[4];
    const int* e3 = (const int*)d_in[5];
    const float* W1 = (const float*)d_in[6];  const float* b1 = (const float*)d_in[7];
    const float* W2 = (const float*)d_in[8];  const float* b2 = (const float*)d_in[9];
    const float* W3 = (const float*)d_in[10]; const float* b3 = (const float*)d_in[11];
    const float* a1w = (const float*)d_in[12]; const float* a1b = (const float*)d_in[13];
    const float* a2w = (const float*)d_in[14]; const float* a2b = (const float*)d_in[15];
    const float* a3w = (const float*)d_in[16]; const float* a3b = (const float*)d_in[17];
    const float* f1w = (const float*)d_in[18]; const float* f1b = (const float*)d_in[19];
    const float* f2w = (const float*)d_in[20]; const float* f2b = (const float*)d_in[21];
    float* out = (float*)d_out;

    static bool attr_set = false;
    if (!attr_set) {
        cudaFuncSetAttribute(fused_kernel, cudaFuncAttributeMaxDynamicSharedMemorySize,
                             SM_TOTAL_F * 4);
        attr_set = true;
    }

    zero_kernel<<<128, 256>>>();
    hist_kernel<<<dim3(256, NG), 256>>>(e1, e2, e3);
    scan_pass1<<<dim3(NSCAN, NG), 256>>>();
    scan_pass2<<<1, 96>>>();
    scan_pass3<<<dim3(NSCAN, NG), 256>>>();
    fill_kernel<<<dim3(256, NG), 256>>>(e1, e2, e3);
    fused_kernel<<<dim3(98, NG), 256, SM_TOTAL_F * 4>>>(x1, x2, x3,
                                                        W1, b1, W2, b2, W3, b3);
    finalize_kernel<<<1, DD>>>(a1w, a1b, a2w, a2b, a3w, a3b, f1w, f1b, f2w, f2b, out);
}